// round 13
// baseline (speedup 1.0000x reference)
#include <cuda_runtime.h>
#include <cstdint>

#define TSTEPS 16384
#define NBATCH 4
#define HDIM   128
#define NCTA   8
#define NTHR   160

// ---------------- device-global scratch (no runtime allocation) ------------
__device__ float g_hs[TSTEPS * NBATCH * HDIM];   // hidden states [t][b][128]
__device__ float g_M[384 * 4];                   // fused W_ih @ W_embed
__device__ float g_C[384];                       // fused bias (incl. b_ih)
__device__ float g_xq[TSTEPS * 20];              // packed x4 per b (16) + use_x flag (16)

// ---------------- helpers --------------------------------------------------
__device__ __forceinline__ void fma2(unsigned long long& d, unsigned long long a,
                                     unsigned long long b) {
    asm("fma.rn.f32x2 %0, %1, %2, %0;" : "+l"(d) : "l"(a), "l"(b));
}
__device__ __forceinline__ float f2sum(unsigned long long v) {
    float lo, hi;
    asm("mov.b64 {%0,%1}, %2;" : "=f"(lo), "=f"(hi) : "l"(v));
    return lo + hi;
}
__device__ __forceinline__ unsigned long long pack2(float lo, float hi) {
    unsigned long long v;
    asm("mov.b64 %0, {%1,%2};" : "=l"(v) : "f"(lo), "f"(hi));
    return v;
}
__device__ __forceinline__ uint32_t smem_u32(const void* p) {
    uint32_t a;
    asm("{ .reg .u64 t; cvta.to.shared.u64 t, %1; cvt.u32.u64 %0, t; }" : "=r"(a) : "l"(p));
    return a;
}
__device__ __forceinline__ float sigm(float x) {
    return __fdividef(1.0f, 1.0f + __expf(-x));
}
__device__ __forceinline__ float tanh_fast(float x) {
    float xc = fminf(fmaxf(x, -15.0f), 15.0f);
    float e = __expf(2.0f * xc);
    return __fdividef(e - 1.0f, e + 1.0f);
}
__device__ __forceinline__ void mbar_wait(uint32_t mb, uint32_t parity) {
    asm volatile(
        "{\n\t"
        ".reg .pred P;\n\t"
        "WL_%=:\n\t"
        "mbarrier.try_wait.parity.acquire.cluster.shared::cta.b64 P, [%0], %1, 0x989680;\n\t"
        "@P bra.uni WD_%=;\n\t"
        "bra.uni WL_%=;\n\t"
        "WD_%=:\n\t"
        "}"
        :: "r"(mb), "r"(parity) : "memory");
}

// ---------------- prep 1: fuse embed into the input-path matvec ------------
__global__ void prep_mc(const float* __restrict__ W_ih, const float* __restrict__ W_embed,
                        const float* __restrict__ b_embed, const float* __restrict__ b_ih) {
    int row = blockIdx.x * blockDim.x + threadIdx.x;
    if (row >= 384) return;
    float m0 = 0.f, m1 = 0.f, m2 = 0.f, m3 = 0.f, c = 0.f;
    for (int k = 0; k < HDIM; k++) {
        float w = W_ih[row * HDIM + k];
        m0 += w * W_embed[k * 4 + 0];
        m1 += w * W_embed[k * 4 + 1];
        m2 += w * W_embed[k * 4 + 2];
        m3 += w * W_embed[k * 4 + 3];
        c  += w * b_embed[k];
    }
    g_M[row * 4 + 0] = m0; g_M[row * 4 + 1] = m1;
    g_M[row * 4 + 2] = m2; g_M[row * 4 + 3] = m3;
    g_C[row] = c + b_ih[row];
}

// ---------------- prep 2: pack per-step inputs -----------------------------
// x = stack([px,py,vx,vy],0).transpose(0,2,1) -> [4, T, B]; model-batch s is
// the SIGNAL index: x[s, t, f] = sig_s[f, t].
__global__ void prep_xq(const float* __restrict__ px, const float* __restrict__ py,
                        const float* __restrict__ vx, const float* __restrict__ vy,
                        const int* __restrict__ mask, const int* __restrict__ cfn) {
    int t = blockIdx.x * blockDim.x + threadIdx.x;
    if (t >= TSTEPS) return;
    int ctx = cfn ? cfn[0] : 8;
    if (ctx < 1) ctx = 1;
    float ux = (t < ctx || mask[t] == 0) ? 1.f : 0.f;
    for (int f = 0; f < 4; f++) {
        g_xq[t * 20 + 0 * 4 + f] = px[f * TSTEPS + t];
        g_xq[t * 20 + 1 * 4 + f] = py[f * TSTEPS + t];
        g_xq[t * 20 + 2 * 4 + f] = vx[f * TSTEPS + t];
        g_xq[t * 20 + 3 * 4 + f] = vy[f * TSTEPS + t];
    }
    g_xq[t * 20 + 16] = ux;
}

// ---------------- sequential GRU: 4 clusters (one per batch) of 8 CTAs -----
// Cluster handles batch b = blockIdx.x/8. CTA rank owns h-cols [16r,16r+16).
// 64 dot rows per CTA: q = rr>>4: 0=rsel, 1=zsel, 2=n_hh, 3=n_ih; j = rr&15.
// Feedback steps: rsel/zsel use Wsum = W_hh+W_ih (one dot covers both gi+gh).
// use_x steps: rsel/zsel use W_hh and add the fused-M input term; n_ih = M·x.
// 128 dot threads (tid = rr*2 + kh; kh = k-half via interleaved 16B chunks),
// weights register-resident. Warp 4 = x prefetch (distance 2).
__global__ void __launch_bounds__(NTHR, 1) __cluster_dims__(NCTA, 1, 1)
gru_seq(const float* __restrict__ W_hh, const float* __restrict__ W_ih,
        const float* __restrict__ b_hh, const float* __restrict__ b_ih) {
    __shared__ float SH[2][HDIM];    // double-buffered h (this batch)
    __shared__ float SP[64];         // dot results
    __shared__ float SX[4][8];       // x-stage ring (distance-2)
    __shared__ __align__(8) unsigned long long s_mbar;

    int tid = threadIdx.x;
    uint32_t rank;
    asm("mov.u32 %0, %%cluster_ctarank;" : "=r"(rank));
    int b = blockIdx.x >> 3;

    // ---- init ----
    for (int i = tid; i < 2 * HDIM; i += NTHR) (&SH[0][0])[i] = 0.f;
    if (tid >= 128 && tid < 133) {
        int l = tid - 128;
        int sel = (l < 4) ? (b * 4 + l) : 16;
        SX[0][l] = g_xq[0 * 20 + sel];
        SX[1][l] = g_xq[1 * 20 + sel];
    }
    uint32_t mb = smem_u32(&s_mbar);
    if (tid == 0)
        asm volatile("mbarrier.init.shared.b64 [%0], %1;" :: "r"(mb), "r"(NCTA) : "memory");

    bool isdot = (tid < 128);
    int rr = tid >> 1, kh = tid & 1;
    int q = tid >> 5;                       // warp id == row-quarter for dot warps
    int j = rr & 15, col = (int)rank * 16 + j;
    int grow = (q == 0) ? col : (q == 1) ? (128 + col) : (256 + col);

    unsigned long long wa[32], wb[32];
    float bias_fb = 0.f, bias_ux = 0.f, ccv = 0.f, m0 = 0.f, m1 = 0.f, m2 = 0.f, m3 = 0.f;
    if (isdot) {
        const float4* hh4 = (const float4*)(W_hh + grow * HDIM);
        const float4* ih4 = (const float4*)(W_ih + grow * HDIM);
#pragma unroll
        for (int i = 0; i < 16; i++) {
            int c = 2 * i + kh;             // interleaved 16B chunks across kh
            float4 a = (q == 3) ? ih4[c] : hh4[c];
            wa[2 * i]     = pack2(a.x, a.y);
            wa[2 * i + 1] = pack2(a.z, a.w);
            if (q <= 1) {
                float4 s4 = ih4[c];
                wb[2 * i]     = pack2(a.x + s4.x, a.y + s4.y);
                wb[2 * i + 1] = pack2(a.z + s4.z, a.w + s4.w);
            } else {
                wb[2 * i] = 0ull; wb[2 * i + 1] = 0ull;
            }
        }
        float bh = b_hh[grow], bi = b_ih[grow];
        if (q <= 1) {
            bias_fb = bh + bi; bias_ux = bh;
            ccv = g_C[grow];
            m0 = g_M[grow * 4 + 0]; m1 = g_M[grow * 4 + 1];
            m2 = g_M[grow * 4 + 2]; m3 = g_M[grow * 4 + 3];
        } else if (q == 2) {
            bias_fb = bh;
        } else {
            bias_fb = bi;
            ccv = g_C[grow];
            m0 = g_M[grow * 4 + 0]; m1 = g_M[grow * 4 + 1];
            m2 = g_M[grow * 4 + 2]; m3 = g_M[grow * 4 + 3];
        }
    }
    __syncthreads();
    asm volatile("barrier.cluster.arrive.aligned;" ::: "memory");
    asm volatile("barrier.cluster.wait.aligned;" ::: "memory");

    for (int t = 0; t < TSTEPS; t++) {
        int par = t & 1;
        int slot = t & 3;
        float ux = SX[slot][4];

        // distance-2 prefetch (warp 4, lanes 0-4)
        float pf = 0.f;
        int l = tid - 128;
        bool dopf = (l >= 0 && l < 5 && (t + 2) < TSTEPS);
        if (dopf) {
            int sel = (l < 4) ? (b * 4 + l) : 16;
            pf = g_xq[(t + 2) * 20 + sel];
        }

        // ---- dot phase (warps 0-3) ----
        if (isdot) {
            bool uxb = (ux != 0.f);
            float tot = 0.f;
            if (!(q == 3 && uxb)) {
                const ulonglong2* hp = (const ulonglong2*)(&SH[par][0]);
                unsigned long long a0 = 0ull, a1 = 0ull;
                if (q <= 1 && !uxb) {
#pragma unroll
                    for (int i = 0; i < 16; i++) {
                        ulonglong2 h2 = hp[2 * i + kh];
                        fma2(a0, wb[2 * i], h2.x);
                        fma2(a1, wb[2 * i + 1], h2.y);
                    }
                } else {
#pragma unroll
                    for (int i = 0; i < 16; i++) {
                        ulonglong2 h2 = hp[2 * i + kh];
                        fma2(a0, wa[2 * i], h2.x);
                        fma2(a1, wa[2 * i + 1], h2.y);
                    }
                }
                tot = f2sum(a0) + f2sum(a1);
            }
            tot += __shfl_xor_sync(0xFFFFFFFFu, tot, 1);
            if (kh == 0) {
                float v;
                if (uxb) {
                    float mx = ccv + m0 * SX[slot][0] + m1 * SX[slot][1]
                                   + m2 * SX[slot][2] + m3 * SX[slot][3];
                    if (q == 3)      v = mx;                 // i_n = M.x + C (incl b_ih)
                    else if (q == 2) v = tot + bias_fb;      // h_n = Whh.h + b_hh
                    else             v = tot + bias_ux + mx; // gate sum: Whh.h+b_hh + Mx+C
                } else {
                    v = tot + bias_fb;
                }
                SP[rr] = v;
            }
        }
        if (dopf) SX[(t + 2) & 3][l] = pf;
        __syncthreads();

        // ---- gate phase (lanes 0-15 of warp 0) ----
        if (tid < 16) {
            int jj = tid, cl = (int)rank * 16 + jj;
            float rg = sigm(SP[jj]);
            float zg = sigm(SP[16 + jj]);
            float ng = tanh_fast(SP[48 + jj] + rg * SP[32 + jj]);
            float hold = SH[par][cl];
            float hn = (1.f - zg) * ng + zg * hold;

            int np = par ^ 1;
            SH[np][cl] = hn;
            uint32_t la = smem_u32(&SH[np][cl]);
#pragma unroll
            for (int p = 0; p < NCTA; p++) {
                if (p == (int)rank) continue;
                uint32_t ra;
                asm("mapa.shared::cluster.u32 %0, %1, %2;" : "=r"(ra) : "r"(la), "r"(p));
                asm volatile("st.shared::cluster.f32 [%0], %1;" :: "r"(ra), "f"(hn));
            }
            g_hs[(t * NBATCH + b) * HDIM + cl] = hn;

            __syncwarp(0x0000FFFFu);
            if (tid == 0) {
                asm volatile("fence.acq_rel.cluster;" ::: "memory");
#pragma unroll
                for (int p = 0; p < NCTA; p++) {
                    uint32_t ra;
                    asm("mapa.shared::cluster.u32 %0, %1, %2;" : "=r"(ra) : "r"(mb), "r"(p));
                    asm volatile("mbarrier.arrive.release.cluster.shared::cluster.b64 _, [%0];"
                                 :: "r"(ra) : "memory");
                }
            }
        }

        // ---- wait for all 8 CTAs' arrives for this step ----
        mbar_wait(mb, (uint32_t)(t & 1));
    }

    asm volatile("barrier.cluster.arrive.aligned;" ::: "memory");
    asm volatile("barrier.cluster.wait.aligned;" ::: "memory");
}

// ---------------- MLP head over all (t,b) rows -----------------------------
__global__ void __launch_bounds__(256, 1)
head_kernel(const float* __restrict__ W1, const float* __restrict__ b1,
            const float* __restrict__ W2, const float* __restrict__ b2,
            const float* __restrict__ W3, const float* __restrict__ b3,
            float* __restrict__ out) {
    extern __shared__ float s[];
    float* sW1 = s;                 // 64*128
    float* sW2 = sW1 + 64 * 128;    // 64*64
    float* sW3 = sW2 + 64 * 64;     // 2*64
    float* sb1 = sW3 + 128;
    float* sb2 = sb1 + 64;
    float* sb3 = sb2 + 64;
    int tid = threadIdx.x;
    for (int i = tid; i < 64 * 128; i += 256) sW1[i] = W1[i];
    for (int i = tid; i < 64 * 64;  i += 256) sW2[i] = W2[i];
    for (int i = tid; i < 128;      i += 256) sW3[i] = W3[i];
    if (tid < 64) { sb1[tid] = b1[tid]; sb2[tid] = b2[tid]; }
    if (tid < 2)  sb3[tid] = b3[tid];
    __syncthreads();

    int row = blockIdx.x * 256 + tid;       // row = t*4 + b
    float h[128];
    const float4* hp = (const float4*)(g_hs + row * HDIM);
#pragma unroll
    for (int i = 0; i < 32; i++) {
        float4 v = hp[i];
        h[i * 4] = v.x; h[i * 4 + 1] = v.y; h[i * 4 + 2] = v.z; h[i * 4 + 3] = v.w;
    }
    float y1[64];
    for (int o = 0; o < 64; o++) {
        float acc = sb1[o];
        const float4* wp = (const float4*)(sW1 + o * 128);
#pragma unroll
        for (int i = 0; i < 32; i++) {
            float4 w = wp[i];
            acc += w.x * h[i * 4] + w.y * h[i * 4 + 1] + w.z * h[i * 4 + 2] + w.w * h[i * 4 + 3];
        }
        y1[o] = acc > 0.f ? acc : expm1f(acc);
    }
    float y2[64];
    for (int o = 0; o < 64; o++) {
        float acc = sb2[o];
        const float4* wp = (const float4*)(sW2 + o * 64);
#pragma unroll
        for (int i = 0; i < 16; i++) {
            float4 w = wp[i];
            acc += w.x * y1[i * 4] + w.y * y1[i * 4 + 1] + w.z * y1[i * 4 + 2] + w.w * y1[i * 4 + 3];
        }
        y2[o] = acc > 0.f ? acc : expm1f(acc);
    }
    float o0 = sb3[0], o1 = sb3[1];
#pragma unroll
    for (int k = 0; k < 64; k++) {
        o0 += sW3[k] * y2[k];
        o1 += sW3[64 + k] * y2[k];
    }
    int t = row >> 2, bb = row & 3;
    out[bb * TSTEPS + t] = o0;
    out[NBATCH * TSTEPS + bb * TSTEPS + t] = o1;
}

// ---------------- launch ---------------------------------------------------
extern "C" void kernel_launch(void* const* d_in, const int* in_sizes, int n_in,
                              void* d_out, int out_size) {
    const float* pos_x   = (const float*)d_in[0];
    const float* pos_y   = (const float*)d_in[1];
    const float* v_x     = (const float*)d_in[2];
    const float* v_y     = (const float*)d_in[3];
    const float* W_embed = (const float*)d_in[4];
    const float* b_embed = (const float*)d_in[5];
    const float* W_ih    = (const float*)d_in[6];
    const float* W_hh    = (const float*)d_in[7];
    const float* b_ih    = (const float*)d_in[8];
    const float* b_hh    = (const float*)d_in[9];
    const float* W1      = (const float*)d_in[10];
    const float* b1      = (const float*)d_in[11];
    const float* W2      = (const float*)d_in[12];
    const float* b2      = (const float*)d_in[13];
    const float* W3      = (const float*)d_in[14];
    const float* b3      = (const float*)d_in[15];
    const int*   mask    = (const int*)d_in[16];
    const int*   cfn     = (n_in > 17) ? (const int*)d_in[17] : nullptr;
    float* out = (float*)d_out;

    const int head_smem = (64 * 128 + 64 * 64 + 128 + 64 + 64 + 2) * 4;
    cudaFuncSetAttribute(head_kernel, cudaFuncAttributeMaxDynamicSharedMemorySize, head_smem);

    prep_mc<<<3, 128>>>(W_ih, W_embed, b_embed, b_ih);
    prep_xq<<<(TSTEPS + 255) / 256, 256>>>(pos_x, pos_y, v_x, v_y, mask, cfn);
    gru_seq<<<NCTA * NBATCH, NTHR>>>(W_hh, W_ih, b_hh, b_ih);
    head_kernel<<<(TSTEPS * NBATCH) / 256, 256, head_smem>>>(W1, b1, W2, b2, W3, b3, out);
}

// round 14
// speedup vs baseline: 2.2724x; 2.2724x over previous
#include <cuda_runtime.h>
#include <cstdint>

#define TSTEPS 16384
#define NBATCH 4
#define HDIM   128
#define NTHR   384

// ---------------- device-global scratch (no runtime allocation) ------------
__device__ float g_hs[TSTEPS * NBATCH * HDIM];   // hidden states [t][b][128]
__device__ float g_M[384 * 4];                   // fused W_ih @ W_embed
__device__ float g_C[384];                       // fused bias (incl. b_ih)
__device__ float g_xq[TSTEPS * 20];              // packed x4 per b (16) + use_x flag (16)

// ---------------- helpers --------------------------------------------------
__device__ __forceinline__ void fma2(unsigned long long& d, unsigned long long a,
                                     unsigned long long b) {
    asm("fma.rn.f32x2 %0, %1, %2, %0;" : "+l"(d) : "l"(a), "l"(b));
}
__device__ __forceinline__ float f2sum(unsigned long long v) {
    float lo, hi;
    asm("mov.b64 {%0,%1}, %2;" : "=f"(lo), "=f"(hi) : "l"(v));
    return lo + hi;
}
__device__ __forceinline__ unsigned long long pack2(float lo, float hi) {
    unsigned long long v;
    asm("mov.b64 %0, {%1,%2};" : "=l"(v) : "f"(lo), "f"(hi));
    return v;
}
__device__ __forceinline__ uint32_t smem_u32(const void* p) {
    uint32_t a;
    asm("{ .reg .u64 t; cvta.to.shared.u64 t, %1; cvt.u32.u64 %0, t; }" : "=r"(a) : "l"(p));
    return a;
}
__device__ __forceinline__ float sigm(float x) {
    return __fdividef(1.0f, 1.0f + __expf(-x));
}
__device__ __forceinline__ float tanh_fast(float x) {
    float xc = fminf(fmaxf(x, -15.0f), 15.0f);
    float e = __expf(2.0f * xc);
    return __fdividef(e - 1.0f, e + 1.0f);
}
__device__ __forceinline__ void mbar_wait(uint32_t mb, uint32_t parity) {
    asm volatile(
        "{\n\t"
        ".reg .pred P;\n\t"
        "WL_%=:\n\t"
        "mbarrier.try_wait.parity.acquire.cluster.shared::cta.b64 P, [%0], %1, 0x989680;\n\t"
        "@P bra.uni WD_%=;\n\t"
        "bra.uni WL_%=;\n\t"
        "WD_%=:\n\t"
        "}"
        :: "r"(mb), "r"(parity) : "memory");
}

// ---------------- prep 1: fuse embed into the input-path matvec ------------
__global__ void prep_mc(const float* __restrict__ W_ih, const float* __restrict__ W_embed,
                        const float* __restrict__ b_embed, const float* __restrict__ b_ih) {
    int row = blockIdx.x * blockDim.x + threadIdx.x;
    if (row >= 384) return;
    float m0 = 0.f, m1 = 0.f, m2 = 0.f, m3 = 0.f, c = 0.f;
    for (int k = 0; k < HDIM; k++) {
        float w = W_ih[row * HDIM + k];
        m0 += w * W_embed[k * 4 + 0];
        m1 += w * W_embed[k * 4 + 1];
        m2 += w * W_embed[k * 4 + 2];
        m3 += w * W_embed[k * 4 + 3];
        c  += w * b_embed[k];
    }
    g_M[row * 4 + 0] = m0; g_M[row * 4 + 1] = m1;
    g_M[row * 4 + 2] = m2; g_M[row * 4 + 3] = m3;
    g_C[row] = c + b_ih[row];
}

// ---------------- prep 2: pack per-step inputs -----------------------------
// x = stack([px,py,vx,vy],0).transpose(0,2,1) -> [4, T, B]; model-batch s is
// the SIGNAL index: x[s, t, f] = sig_s[f, t].
__global__ void prep_xq(const float* __restrict__ px, const float* __restrict__ py,
                        const float* __restrict__ vx, const float* __restrict__ vy,
                        const int* __restrict__ mask, const int* __restrict__ cfn) {
    int t = blockIdx.x * blockDim.x + threadIdx.x;
    if (t >= TSTEPS) return;
    int ctx = cfn ? cfn[0] : 8;
    if (ctx < 1) ctx = 1;
    float ux = (t < ctx || mask[t] == 0) ? 1.f : 0.f;
    for (int f = 0; f < 4; f++) {
        g_xq[t * 20 + 0 * 4 + f] = px[f * TSTEPS + t];
        g_xq[t * 20 + 1 * 4 + f] = py[f * TSTEPS + t];
        g_xq[t * 20 + 2 * 4 + f] = vx[f * TSTEPS + t];
        g_xq[t * 20 + 3 * 4 + f] = vy[f * TSTEPS + t];
    }
    g_xq[t * 20 + 16] = ux;
}

// ---------------- sequential GRU: 4 clusters (one per batch) of 2 CTAs -----
// Cluster handles batch b = blockIdx.x/2. CTA rank owns h-cols [64r, 64r+64).
// 384 threads, role = tid/64, j = tid%64, col = rank*64 + j:
//   role 0: Wsum_rz r-row (grow=col)        active on feedback
//   role 1: Wsum_rz z-row (grow=128+col)    active on feedback
//   role 2: W_hh   r-row (grow=col)         active on use_x (+ M.x term)
//   role 3: W_hh   z-row (grow=128+col)     active on use_x (+ M.x term)
//   role 4: W_hh   n-row (grow=256+col)     always active
//   role 5: W_ih   n-row (grow=256+col)     dot on feedback; M.x on use_x
// Weights register-resident (64 u64/thread), k-chunks reordered local-half
// first so the single peer-half mbarrier wait overlaps part-1 compute.
__global__ void __launch_bounds__(NTHR, 1) __cluster_dims__(2, 1, 1)
gru_seq(const float* __restrict__ W_hh, const float* __restrict__ W_ih,
        const float* __restrict__ b_hh, const float* __restrict__ b_ih) {
    __shared__ __align__(16) float SH[2][HDIM];  // double-buffered h
    __shared__ float SP[256];                    // gate pre-activations
    __shared__ float SX[4][8];                   // x-stage ring (distance-2)
    __shared__ __align__(8) unsigned long long s_mbar;

    int tid = threadIdx.x;
    uint32_t rank;
    asm("mov.u32 %0, %%cluster_ctarank;" : "=r"(rank));
    uint32_t peer = rank ^ 1u;
    int b = blockIdx.x >> 1;

    // ---- init smem ----
    for (int i = tid; i < 2 * HDIM; i += NTHR) (&SH[0][0])[i] = 0.f;
    if (tid < 5) {
        int sel = (tid < 4) ? (b * 4 + tid) : 16;
        SX[0][tid] = g_xq[0 * 20 + sel];
        SX[1][tid] = g_xq[1 * 20 + sel];
    }
    uint32_t mb = smem_u32(&s_mbar);
    if (tid == 0)
        asm volatile("mbarrier.init.shared.b64 [%0], %1;" :: "r"(mb), "r"(2) : "memory");

    // ---- per-thread role & weights ----
    int j = tid & 63;
    int role = tid >> 6;
    int col = (int)rank * 64 + j;
    int grow = (role == 0 || role == 2) ? col
             : (role == 1 || role == 3) ? (128 + col) : (256 + col);
    bool bank_sum = (role <= 1);
    bool bank_ih  = (role == 5);

    unsigned long long w[64];
    {
        const float4* hh4 = (const float4*)(W_hh + grow * HDIM);
        const float4* ih4 = (const float4*)(W_ih + grow * HDIM);
#pragma unroll
        for (int i = 0; i < 16; i++) {
            int c1 = (int)rank * 16 + i;   // local-half chunk
            int c2 = c1 ^ 16;              // peer-half chunk
            float4 a = bank_ih ? ih4[c1] : hh4[c1];
            if (bank_sum) { float4 s = ih4[c1]; a.x += s.x; a.y += s.y; a.z += s.z; a.w += s.w; }
            w[2 * i]     = pack2(a.x, a.y);
            w[2 * i + 1] = pack2(a.z, a.w);
            float4 q = bank_ih ? ih4[c2] : hh4[c2];
            if (bank_sum) { float4 s = ih4[c2]; q.x += s.x; q.y += s.y; q.z += s.z; q.w += s.w; }
            w[32 + 2 * i] = pack2(q.x, q.y);
            w[33 + 2 * i] = pack2(q.z, q.w);
        }
    }
    float bh = b_hh[grow], bi = b_ih[grow];
    float bsum = bh + bi;
    float m0 = 0.f, m1 = 0.f, m2 = 0.f, m3 = 0.f, cc = 0.f;
    if (role == 2 || role == 3 || role == 5) {
        m0 = g_M[grow * 4 + 0]; m1 = g_M[grow * 4 + 1];
        m2 = g_M[grow * 4 + 2]; m3 = g_M[grow * 4 + 3];
        cc = g_C[grow];
    }

    // precomputed peer addresses (mapa once)
    uint32_t sh_base = smem_u32(&SH[0][0]);
    uint32_t peer_sh, peer_mb;
    asm("mapa.shared::cluster.u32 %0, %1, %2;" : "=r"(peer_sh) : "r"(sh_base), "r"(peer));
    asm("mapa.shared::cluster.u32 %0, %1, %2;" : "=r"(peer_mb) : "r"(mb), "r"(peer));

    __syncthreads();
    asm volatile("barrier.cluster.arrive.aligned;" ::: "memory");
    asm volatile("barrier.cluster.wait.aligned;" ::: "memory");

    int base1 = (int)rank * 16;
    int base2 = base1 ^ 16;

    for (int t = 0; t < TSTEPS; t++) {
        int slot = t & 3, par = t & 1, np = par ^ 1;
        float ux = SX[slot][4];
        bool uxb = (ux != 0.f);
        bool active = uxb ? (role >= 2 && role <= 4) : (role <= 1 || role >= 4);

        // distance-2 x prefetch issue (stored at end of iteration)
        float pf = 0.f;
        bool dopf = (tid < 5) && (t + 2 < TSTEPS);
        if (dopf) {
            int sel = (tid < 4) ? (b * 4 + tid) : 16;
            pf = g_xq[(t + 2) * 20 + sel];
        }

        // ---- dot part 1: local half of h ----
        unsigned long long a0 = 0ull, a1 = 0ull;
        const ulonglong2* hp = (const ulonglong2*)(&SH[par][0]);
        if (active) {
#pragma unroll
            for (int i = 0; i < 16; i++) {
                ulonglong2 h2 = hp[base1 + i];
                fma2(a0, w[2 * i], h2.x);
                fma2(a1, w[2 * i + 1], h2.y);
            }
        }

        // ---- wait for peer half of h_t (arrived during peer's gate t-1) ----
        if (t > 0) mbar_wait(mb, (uint32_t)((t - 1) & 1));

        // ---- dot part 2: peer half ----
        if (active) {
#pragma unroll
            for (int i = 0; i < 16; i++) {
                ulonglong2 h2 = hp[base2 + i];
                fma2(a0, w[32 + 2 * i], h2.x);
                fma2(a1, w[33 + 2 * i], h2.y);
            }
        }
        float val = f2sum(a0) + f2sum(a1);

        // ---- combine + write SP ----
        if (uxb) {
            float mx = m0 * SX[slot][0] + m1 * SX[slot][1]
                     + m2 * SX[slot][2] + m3 * SX[slot][3] + cc;
            if (role == 2)      SP[j]        = val + bh + mx;
            else if (role == 3) SP[64 + j]   = val + bh + mx;
            else if (role == 4) SP[128 + j]  = val + bh;
            else if (role == 5) SP[192 + j]  = mx;           // i_n = M.x + C
        } else {
            if (role == 0)      SP[j]        = val + bsum;
            else if (role == 1) SP[64 + j]   = val + bsum;
            else if (role == 4) SP[128 + j]  = val + bh;
            else if (role == 5) SP[192 + j]  = val + bi;
        }
        __syncthreads();

        // ---- gate phase: 64 threads (warps 0-1), one h-column each ----
        if (tid < 64) {
            float rg = sigm(SP[j]);
            float zg = sigm(SP[64 + j]);
            float ng = tanh_fast(SP[192 + j] + rg * SP[128 + j]);
            float hold = SH[par][col];
            float hn = (1.f - zg) * ng + zg * hold;

            SH[np][col] = hn;  // local copy
            uint32_t ra = peer_sh + (uint32_t)((np * HDIM + col) * 4);
            asm volatile("st.shared::cluster.f32 [%0], %1;" :: "r"(ra), "f"(hn));
            g_hs[(t * NBATCH + b) * HDIM + col] = hn;

            __syncwarp();
            if ((tid & 31) == 0)
                asm volatile("mbarrier.arrive.release.cluster.shared::cluster.b64 _, [%0];"
                             :: "r"(peer_mb) : "memory");
        }
        if (dopf) SX[(t + 2) & 3][tid] = pf;
        __syncthreads();
    }

    asm volatile("barrier.cluster.arrive.aligned;" ::: "memory");
    asm volatile("barrier.cluster.wait.aligned;" ::: "memory");
}

// ---------------- MLP head over all (t,b) rows -----------------------------
__global__ void __launch_bounds__(256, 1)
head_kernel(const float* __restrict__ W1, const float* __restrict__ b1,
            const float* __restrict__ W2, const float* __restrict__ b2,
            const float* __restrict__ W3, const float* __restrict__ b3,
            float* __restrict__ out) {
    extern __shared__ float s[];
    float* sW1 = s;                 // 64*128
    float* sW2 = sW1 + 64 * 128;    // 64*64
    float* sW3 = sW2 + 64 * 64;     // 2*64
    float* sb1 = sW3 + 128;
    float* sb2 = sb1 + 64;
    float* sb3 = sb2 + 64;
    int tid = threadIdx.x;
    for (int i = tid; i < 64 * 128; i += 256) sW1[i] = W1[i];
    for (int i = tid; i < 64 * 64;  i += 256) sW2[i] = W2[i];
    for (int i = tid; i < 128;      i += 256) sW3[i] = W3[i];
    if (tid < 64) { sb1[tid] = b1[tid]; sb2[tid] = b2[tid]; }
    if (tid < 2)  sb3[tid] = b3[tid];
    __syncthreads();

    int row = blockIdx.x * 256 + tid;       // row = t*4 + b
    float h[128];
    const float4* hp = (const float4*)(g_hs + row * HDIM);
#pragma unroll
    for (int i = 0; i < 32; i++) {
        float4 v = hp[i];
        h[i * 4] = v.x; h[i * 4 + 1] = v.y; h[i * 4 + 2] = v.z; h[i * 4 + 3] = v.w;
    }
    float y1[64];
    for (int o = 0; o < 64; o++) {
        float acc = sb1[o];
        const float4* wp = (const float4*)(sW1 + o * 128);
#pragma unroll
        for (int i = 0; i < 32; i++) {
            float4 w = wp[i];
            acc += w.x * h[i * 4] + w.y * h[i * 4 + 1] + w.z * h[i * 4 + 2] + w.w * h[i * 4 + 3];
        }
        y1[o] = acc > 0.f ? acc : expm1f(acc);
    }
    float y2[64];
    for (int o = 0; o < 64; o++) {
        float acc = sb2[o];
        const float4* wp = (const float4*)(sW2 + o * 64);
#pragma unroll
        for (int i = 0; i < 16; i++) {
            float4 w = wp[i];
            acc += w.x * y1[i * 4] + w.y * y1[i * 4 + 1] + w.z * y1[i * 4 + 2] + w.w * y1[i * 4 + 3];
        }
        y2[o] = acc > 0.f ? acc : expm1f(acc);
    }
    float o0 = sb3[0], o1 = sb3[1];
#pragma unroll
    for (int k = 0; k < 64; k++) {
        o0 += sW3[k] * y2[k];
        o1 += sW3[64 + k] * y2[k];
    }
    int t = row >> 2, bb = row & 3;
    out[bb * TSTEPS + t] = o0;
    out[NBATCH * TSTEPS + bb * TSTEPS + t] = o1;
}

// ---------------- launch ---------------------------------------------------
extern "C" void kernel_launch(void* const* d_in, const int* in_sizes, int n_in,
                              void* d_out, int out_size) {
    const float* pos_x   = (const float*)d_in[0];
    const float* pos_y   = (const float*)d_in[1];
    const float* v_x     = (const float*)d_in[2];
    const float* v_y     = (const float*)d_in[3];
    const float* W_embed = (const float*)d_in[4];
    const float* b_embed = (const float*)d_in[5];
    const float* W_ih    = (const float*)d_in[6];
    const float* W_hh    = (const float*)d_in[7];
    const float* b_ih    = (const float*)d_in[8];
    const float* b_hh    = (const float*)d_in[9];
    const float* W1      = (const float*)d_in[10];
    const float* b1      = (const float*)d_in[11];
    const float* W2      = (const float*)d_in[12];
    const float* b2      = (const float*)d_in[13];
    const float* W3      = (const float*)d_in[14];
    const float* b3      = (const float*)d_in[15];
    const int*   mask    = (const int*)d_in[16];
    const int*   cfn     = (n_in > 17) ? (const int*)d_in[17] : nullptr;
    float* out = (float*)d_out;

    const int head_smem = (64 * 128 + 64 * 64 + 128 + 64 + 64 + 2) * 4;
    cudaFuncSetAttribute(head_kernel, cudaFuncAttributeMaxDynamicSharedMemorySize, head_smem);

    prep_mc<<<3, 128>>>(W_ih, W_embed, b_embed, b_ih);
    prep_xq<<<(TSTEPS + 255) / 256, 256>>>(pos_x, pos_y, v_x, v_y, mask, cfn);
    gru_seq<<<2 * NBATCH, NTHR>>>(W_hh, W_ih, b_hh, b_ih);
    head_kernel<<<(TSTEPS * NBATCH) / 256, 256, head_smem>>>(W1, b1, W2, b2, W3, b3, out);
}